// round 9
// baseline (speedup 1.0000x reference)
#include <cuda_runtime.h>
#include <cuda_bf16.h>
#include <math.h>

#define Sдим 4
#define FF   1128
#define TT   1000
#define DD   13
#define SF   (Sдим*FF)        // 4512
#define NUP  91               // upper-tri incl diag of 13x13
#define NACC (DD + NUP)       // 104
#define KSPLIT 64
#define HID  1000

// -------------------- device scratch (no allocations allowed) --------------------
__device__ float g_mean[2 * SF * DD];
__device__ float g_cov [2 * SF * DD * DD];
__device__ float g_feats[SF];
__device__ float g_h0[4 * FF];
__device__ float g_hA[4 * FF];
__device__ float g_hB[4 * FF];
__device__ float g_partial[KSPLIT * 4 * HID];

// ==================== Kernel 1: moments (mean + cov) ====================
// grid = 2*SF blocks (p tensors then q tensors), 256 threads.
__global__ __launch_bounds__(256) void moments_kernel(
    const float* __restrict__ p, const float* __restrict__ q,
    const float* __restrict__ plen, const float* __restrict__ qlen)
{
    int id    = blockIdx.x;
    int which = (id >= SF) ? 1 : 0;
    int sf    = which ? (id - SF) : id;
    const float* v    = which ? q : p;
    const float* lens = which ? qlen : plen;
    const float* base = v + (size_t)sf * (TT * DD);

    float ms[DD];
    float cp[NUP];
#pragma unroll
    for (int i = 0; i < DD; i++) ms[i] = 0.f;
#pragma unroll
    for (int i = 0; i < NUP; i++) cp[i] = 0.f;

    for (int t = threadIdx.x; t < TT; t += 256) {
        const float* fr = base + t * DD;
        float x[DD];
#pragma unroll
        for (int i = 0; i < DD; i++) x[i] = __ldg(fr + i);
#pragma unroll
        for (int i = 0; i < DD; i++) ms[i] += x[i];
#pragma unroll
        for (int i = 0; i < DD; i++) {
#pragma unroll
            for (int j = 0; j <= i; j++) {
                cp[i * (i + 1) / 2 + j] += x[i] * x[j];
            }
        }
    }

    // warp reduce all 104 accumulators
    const unsigned FULL = 0xffffffffu;
#pragma unroll
    for (int i = 0; i < DD; i++) {
#pragma unroll
        for (int o = 16; o > 0; o >>= 1) ms[i] += __shfl_down_sync(FULL, ms[i], o);
    }
#pragma unroll
    for (int i = 0; i < NUP; i++) {
#pragma unroll
        for (int o = 16; o > 0; o >>= 1) cp[i] += __shfl_down_sync(FULL, cp[i], o);
    }

    __shared__ float red[8][NACC];
    __shared__ float fmean[DD];
    int w = threadIdx.x >> 5, lane = threadIdx.x & 31;
    if (lane == 0) {
#pragma unroll
        for (int i = 0; i < DD; i++)  red[w][i]      = ms[i];
#pragma unroll
        for (int i = 0; i < NUP; i++) red[w][DD + i] = cp[i];
    }
    __syncthreads();

    float invlen = 1.f / lens[sf];

    if (threadIdx.x < DD) {
        float s = 0.f;
#pragma unroll
        for (int ww = 0; ww < 8; ww++) s += red[ww][threadIdx.x];
        float mn = s * invlen;
        fmean[threadIdx.x] = mn;
        g_mean[(size_t)(which * SF + sf) * DD + threadIdx.x] = mn;
    }
    __syncthreads();

    if (threadIdx.x < NUP) {
        float s = 0.f;
#pragma unroll
        for (int ww = 0; ww < 8; ww++) s += red[ww][DD + threadIdx.x];
        // map linear upper-tri index -> (i,j), j<=i
        int li = (int)threadIdx.x;
        int i = 0;
        while ((i + 1) * (i + 2) / 2 <= li) i++;
        int j = li - i * (i + 1) / 2;
        float cv = s * invlen - fmean[i] * fmean[j];
        if (i == j) cv += 1e-3f;
        float* C = g_cov + (size_t)(which * SF + sf) * (DD * DD);
        C[i * DD + j] = cv;
        C[j * DD + i] = cv;
    }
}

// ==================== Kernel 2: symmetric KL (warp per pair) ====================
__global__ __launch_bounds__(256) void kl_kernel(const float* __restrict__ mask)
{
    const unsigned FULL = 0xffffffffu;
    int gw   = (blockIdx.x * blockDim.x + threadIdx.x) >> 5;  // grid sized so gw < SF always
    int lane = threadIdx.x & 31;
    bool act = (lane < DD);

    const float* pm = g_mean + (size_t)gw * DD;
    const float* qm = g_mean + (size_t)(SF + gw) * DD;
    const float* PC = g_cov  + (size_t)gw * (DD * DD);
    const float* QC = g_cov  + (size_t)(SF + gw) * (DD * DD);

    float pc[DD], qc[DD], df[DD];
    float dl = 0.f;
    if (act) dl = pm[lane] - qm[lane];
#pragma unroll
    for (int i = 0; i < DD; i++) df[i] = __shfl_sync(FULL, dl, i);
#pragma unroll
    for (int i = 0; i < DD; i++) {
        pc[i] = act ? PC[lane * DD + i] : 0.f;
        qc[i] = act ? QC[lane * DD + i] : 0.f;
    }

    float total = 0.f;

    // ---- two passes: invert qcov (pair with pc), then invert pcov (pair with qc)
#pragma unroll
    for (int pass = 0; pass < 2; pass++) {
        float a[DD];
#pragma unroll
        for (int i = 0; i < DD; i++) a[i] = (pass == 0) ? qc[i] : pc[i];

        // Cholesky (lower), lane = row, fully unrolled, shuffle broadcasts
#pragma unroll
        for (int k = 0; k < DD; k++) {
            float dkk  = __shfl_sync(FULL, a[k], k);
            float linv = rsqrtf(dkk);
            float lk   = a[k] * linv;   // L[lane][k] for lane>=k
            a[k] = lk;
#pragma unroll
            for (int j = k + 1; j < DD; j++) {
                float ljk = __shfl_sync(FULL, lk, j);
                a[j] -= lk * ljk;
            }
        }

        float dinv[DD];
#pragma unroll
        for (int i = 0; i < DD; i++) dinv[i] = 1.f / __shfl_sync(FULL, a[i], i);

        // lane j computes column j of (L L^T)^{-1}
        float y[DD], x[DD];
#pragma unroll
        for (int i = 0; i < DD; i++) {
            float acc = (lane == i) ? 1.f : 0.f;
#pragma unroll
            for (int k = 0; k < i; k++) {
                float Lik = __shfl_sync(FULL, a[k], i);   // L[i][k]
                acc -= Lik * y[k];
            }
            y[i] = acc * dinv[i];
        }
#pragma unroll
        for (int i = DD - 1; i >= 0; i--) {
            float acc = y[i];
#pragma unroll
            for (int k = i + 1; k < DD; k++) {
                float Lki = __shfl_sync(FULL, a[i], k);   // L[k][i]
                acc -= Lki * x[k];
            }
            x[i] = acc * dinv[i];
        }

        // contribution: tr(inv * other) column j + diff^T inv diff column j
        float tr_c = 0.f, qd_c = 0.f;
#pragma unroll
        for (int i = 0; i < DD; i++) {
            float oc = (pass == 0) ? pc[i] : qc[i];
            tr_c += x[i] * oc;
            qd_c += x[i] * df[i];
        }
        float c = act ? (tr_c + dl * qd_c) : 0.f;
        total += c;
    }

    // warp reduce
#pragma unroll
    for (int o = 16; o > 0; o >>= 1) total += __shfl_down_sync(FULL, total, o);

    if (lane == 0) {
        float kl   = 0.25f * (total - 2.f * DD);
        float feat = logf(kl + 1e-5f);
        feat = (feat + 1.f) * mask[gw] - 1.f;
        g_feats[gw] = feat;
    }
}

// ==================== Kernel 3: BatchNorm over S=4 ====================
__global__ void bn_kernel(const float* __restrict__ gamma, const float* __restrict__ beta)
{
    int f = blockIdx.x * blockDim.x + threadIdx.x;
    if (f >= FF) return;
    float v0 = g_feats[f];
    float v1 = g_feats[FF + f];
    float v2 = g_feats[2 * FF + f];
    float v3 = g_feats[3 * FF + f];
    float mu = 0.25f * (v0 + v1 + v2 + v3);
    float d0 = v0 - mu, d1 = v1 - mu, d2 = v2 - mu, d3 = v3 - mu;
    float var = 0.25f * (d0 * d0 + d1 * d1 + d2 * d2 + d3 * d3);
    float sc  = rsqrtf(var + 1e-5f) * gamma[f];
    float bb  = beta[f];
    g_h0[f]          = d0 * sc + bb;
    g_h0[FF + f]     = d1 * sc + bb;
    g_h0[2 * FF + f] = d2 * sc + bb;
    g_h0[3 * FF + f] = d3 * sc + bb;
}

// ==================== Kernel 4: split-K GEMM partial (4 x din @ din x dout) ====================
// grid.x = KSPLIT. thread handles 4 adjacent output columns (float4 W loads, coalesced).
__global__ __launch_bounds__(256) void gemm_part(
    const float* __restrict__ hin, const float* __restrict__ W, int din, int dout)
{
    int tid = threadIdx.x;
    int nc4 = (dout + 3) >> 2;
    if (tid >= nc4) return;
    int c0 = tid * 4;
    int chunk = (din + KSPLIT - 1) / KSPLIT;
    int k0 = blockIdx.x * chunk;
    int k1 = min(din, k0 + chunk);

    float4 a0 = {0,0,0,0}, a1 = {0,0,0,0}, a2 = {0,0,0,0}, a3 = {0,0,0,0};
    for (int k = k0; k < k1; k++) {
        float4 w = __ldg(reinterpret_cast<const float4*>(W + (size_t)k * dout + c0));
        float h0 = __ldg(hin + k);
        float h1 = __ldg(hin + din + k);
        float h2 = __ldg(hin + 2 * din + k);
        float h3 = __ldg(hin + 3 * din + k);
        a0.x += h0 * w.x; a0.y += h0 * w.y; a0.z += h0 * w.z; a0.w += h0 * w.w;
        a1.x += h1 * w.x; a1.y += h1 * w.y; a1.z += h1 * w.z; a1.w += h1 * w.w;
        a2.x += h2 * w.x; a2.y += h2 * w.y; a2.z += h2 * w.z; a2.w += h2 * w.w;
        a3.x += h3 * w.x; a3.y += h3 * w.y; a3.z += h3 * w.z; a3.w += h3 * w.w;
    }
    float* P = g_partial + (size_t)blockIdx.x * 4 * dout;
    *reinterpret_cast<float4*>(P + 0 * dout + c0) = a0;
    *reinterpret_cast<float4*>(P + 1 * dout + c0) = a1;
    *reinterpret_cast<float4*>(P + 2 * dout + c0) = a2;
    *reinterpret_cast<float4*>(P + 3 * dout + c0) = a3;
}

// ==================== Kernel 5: split-K reduce + bias + relu ====================
__global__ void reduce_kernel(const float* __restrict__ bias, float* __restrict__ hout,
                              int dout, int relu)
{
    int idx = blockIdx.x * blockDim.x + threadIdx.x;
    if (idx >= 4 * dout) return;
    int c = idx % dout;
    float s = 0.f;
#pragma unroll 8
    for (int b = 0; b < KSPLIT; b++) s += g_partial[(size_t)b * 4 * dout + idx];
    s += bias[c];
    if (relu) s = fmaxf(s, 0.f);
    hout[idx] = s;
}

// ==================== Kernel 6: final layer (1000 -> 1) ====================
__global__ void final_kernel(const float* __restrict__ h, const float* __restrict__ W7,
                             const float* __restrict__ b7, float* __restrict__ out)
{
    const unsigned FULL = 0xffffffffu;
    int tid = threadIdx.x; // 128 threads
    float acc[4] = {0.f, 0.f, 0.f, 0.f};
    for (int k = tid; k < HID; k += 128) {
        float w = W7[k];
#pragma unroll
        for (int r = 0; r < 4; r++) acc[r] += h[r * HID + k] * w;
    }
#pragma unroll
    for (int r = 0; r < 4; r++) {
#pragma unroll
        for (int o = 16; o > 0; o >>= 1) acc[r] += __shfl_down_sync(FULL, acc[r], o);
    }
    __shared__ float red[4][4];
    int w = tid >> 5, lane = tid & 31;
    if (lane == 0) {
#pragma unroll
        for (int r = 0; r < 4; r++) red[w][r] = acc[r];
    }
    __syncthreads();
    if (tid < 4) {
        float s = red[0][tid] + red[1][tid] + red[2][tid] + red[3][tid] + b7[0];
        out[tid] = s;
    }
}

// ==================== launch ====================
extern "C" void kernel_launch(void* const* d_in, const int* in_sizes, int n_in,
                              void* d_out, int out_size)
{
    const float* p_vects = (const float*)d_in[0];
    const float* q_vects = (const float*)d_in[1];
    const float* p_len   = (const float*)d_in[2];
    const float* q_len   = (const float*)d_in[3];
    const float* mask    = (const float*)d_in[4];
    const float* gamma   = (const float*)d_in[5];
    const float* beta    = (const float*)d_in[6];
    const float* W1 = (const float*)d_in[7];  const float* b1 = (const float*)d_in[8];
    const float* W2 = (const float*)d_in[9];  const float* b2 = (const float*)d_in[10];
    const float* W3 = (const float*)d_in[11]; const float* b3 = (const float*)d_in[12];
    const float* W4 = (const float*)d_in[13]; const float* b4 = (const float*)d_in[14];
    const float* W5 = (const float*)d_in[15]; const float* b5 = (const float*)d_in[16];
    const float* W6 = (const float*)d_in[17]; const float* b6 = (const float*)d_in[18];
    const float* W7 = (const float*)d_in[19]; const float* b7 = (const float*)d_in[20];
    float* out = (float*)d_out;

    float* hA; cudaGetSymbolAddress((void**)&hA, g_hA);
    float* hB; cudaGetSymbolAddress((void**)&hB, g_hB);
    float* h0; cudaGetSymbolAddress((void**)&h0, g_h0);

    // 1. moments for p (blocks 0..SF-1) and q (blocks SF..2SF-1)
    moments_kernel<<<2 * SF, 256>>>(p_vects, q_vects, p_len, q_len);

    // 2. symmetric KL: one warp per (s,f). 4512 warps = 564 blocks x 8 warps (exact)
    kl_kernel<<<SF / 8, 256>>>(mask);

    // 3. batch norm -> h0 [4,1128]
    bn_kernel<<<(FF + 255) / 256, 256>>>(gamma, beta);

    // 4. MLP
    // layer 1: 1128 -> 1000
    gemm_part<<<KSPLIT, 256>>>(h0, W1, FF, HID);
    reduce_kernel<<<(4 * HID + 255) / 256, 256>>>(b1, hA, HID, 1);
    // layer 2
    gemm_part<<<KSPLIT, 256>>>(hA, W2, HID, HID);
    reduce_kernel<<<(4 * HID + 255) / 256, 256>>>(b2, hB, HID, 1);
    // layer 3
    gemm_part<<<KSPLIT, 256>>>(hB, W3, HID, HID);
    reduce_kernel<<<(4 * HID + 255) / 256, 256>>>(b3, hA, HID, 1);
    // layer 4
    gemm_part<<<KSPLIT, 256>>>(hA, W4, HID, HID);
    reduce_kernel<<<(4 * HID + 255) / 256, 256>>>(b4, hB, HID, 1);
    // layer 5
    gemm_part<<<KSPLIT, 256>>>(hB, W5, HID, HID);
    reduce_kernel<<<(4 * HID + 255) / 256, 256>>>(b5, hA, HID, 1);
    // layer 6
    gemm_part<<<KSPLIT, 256>>>(hA, W6, HID, HID);
    reduce_kernel<<<(4 * HID + 255) / 256, 256>>>(b6, hB, HID, 1);
    // layer 7: 1000 -> 1
    final_kernel<<<1, 128>>>(hB, W7, b7, out);
}

// round 10
// speedup vs baseline: 1.6334x; 1.6334x over previous
#include <cuda_runtime.h>
#include <cuda_bf16.h>
#include <math.h>

#define SS   4
#define FF   1128
#define TT   1000
#define DD   13
#define SF   (SS*FF)          // 4512
#define NT   (2*SF)           // 9024 tensors (p then q)
#define NUP  91               // upper-tri incl diag of 13x13
#define KS   125              // split-K factor for MLP gemms
#define HID  1000

// -------------------- device scratch (no allocations allowed) --------------------
__device__ float g_mean[NT * DD];
__device__ float g_cov [NT * DD * DD];
__device__ float g_feats[SF];
__device__ float g_h0[4 * FF];
__device__ float g_hA[4 * FF];
__device__ float g_hB[4 * FF];
__device__ float g_partial[KS * 4 * HID];

// ==================== Kernel 1: moments (mean + cov), one warp per tensor ====================
// grid = NT/4 CTAs of 128 threads (4 warps). Warp w handles tensor blockIdx.x*4 + w.
// Each lane processes 4-frame chunks (208B, float4-aligned) strided by 32.
__global__ __launch_bounds__(128) void moments_kernel(
    const float* __restrict__ p, const float* __restrict__ q,
    const float* __restrict__ plen, const float* __restrict__ qlen)
{
    const unsigned FULL = 0xffffffffu;
    int wid  = threadIdx.x >> 5;
    int lane = threadIdx.x & 31;
    int tid  = blockIdx.x * 4 + wid;           // tensor id, < NT

    int which = (tid >= SF) ? 1 : 0;
    int sf    = which ? (tid - SF) : tid;
    const float* v    = which ? q : p;
    const float* lens = which ? qlen : plen;
    const float4* base4 = reinterpret_cast<const float4*>(v + (size_t)sf * (TT * DD));

    float ms[DD];
    float cp[NUP];
#pragma unroll
    for (int i = 0; i < DD; i++) ms[i] = 0.f;
#pragma unroll
    for (int i = 0; i < NUP; i++) cp[i] = 0.f;

    // 250 chunks of 4 frames (4*13 floats = 13 float4)
    for (int c = lane; c < 250; c += 32) {
        const float4* p4 = base4 + c * 13;
        float fl[52];
#pragma unroll
        for (int m = 0; m < 13; m++) {
            float4 w = __ldg(p4 + m);
            fl[4 * m + 0] = w.x; fl[4 * m + 1] = w.y;
            fl[4 * m + 2] = w.z; fl[4 * m + 3] = w.w;
        }
#pragma unroll
        for (int f = 0; f < 4; f++) {
            const float* x = fl + 13 * f;
#pragma unroll
            for (int i = 0; i < DD; i++) ms[i] += x[i];
#pragma unroll
            for (int i = 0; i < DD; i++) {
#pragma unroll
                for (int j = 0; j <= i; j++) {
                    cp[i * (i + 1) / 2 + j] += x[i] * x[j];
                }
            }
        }
    }

    // warp-level tree reduction of all 104 accumulators
#pragma unroll
    for (int i = 0; i < DD; i++) {
#pragma unroll
        for (int o = 16; o > 0; o >>= 1) ms[i] += __shfl_down_sync(FULL, ms[i], o);
    }
#pragma unroll
    for (int i = 0; i < NUP; i++) {
#pragma unroll
        for (int o = 16; o > 0; o >>= 1) cp[i] += __shfl_down_sync(FULL, cp[i], o);
    }

    __shared__ float s_sum[4][DD + NUP];
    __shared__ float s_mean[4][DD];
    if (lane == 0) {
#pragma unroll
        for (int i = 0; i < DD; i++)  s_sum[wid][i]      = ms[i];
#pragma unroll
        for (int i = 0; i < NUP; i++) s_sum[wid][DD + i] = cp[i];
    }
    __syncwarp();

    float invlen = 1.f / __ldg(lens + sf);

    if (lane < DD) {
        float mn = s_sum[wid][lane] * invlen;
        s_mean[wid][lane] = mn;
        g_mean[(size_t)tid * DD + lane] = mn;
    }
    __syncwarp();

    float* C = g_cov + (size_t)tid * (DD * DD);
    for (int e = lane; e < NUP; e += 32) {
        int i = 0;
        while ((i + 1) * (i + 2) / 2 <= e) i++;
        int j = e - i * (i + 1) / 2;
        float cv = s_sum[wid][DD + e] * invlen - s_mean[wid][i] * s_mean[wid][j];
        if (i == j) cv += 1e-3f;
        C[i * DD + j] = cv;
        C[j * DD + i] = cv;
    }
}

// ==================== Kernel 2: symmetric KL (warp per pair) ====================
__global__ __launch_bounds__(256) void kl_kernel(const float* __restrict__ mask)
{
    const unsigned FULL = 0xffffffffu;
    int gw   = (blockIdx.x * blockDim.x + threadIdx.x) >> 5;  // < SF by grid sizing
    int lane = threadIdx.x & 31;
    bool act = (lane < DD);

    const float* pm = g_mean + (size_t)gw * DD;
    const float* qm = g_mean + (size_t)(SF + gw) * DD;
    const float* PC = g_cov  + (size_t)gw * (DD * DD);
    const float* QC = g_cov  + (size_t)(SF + gw) * (DD * DD);

    float pc[DD], qc[DD], df[DD];
    float dl = 0.f;
    if (act) dl = pm[lane] - qm[lane];
#pragma unroll
    for (int i = 0; i < DD; i++) df[i] = __shfl_sync(FULL, dl, i);
#pragma unroll
    for (int i = 0; i < DD; i++) {
        pc[i] = act ? PC[lane * DD + i] : 0.f;
        qc[i] = act ? QC[lane * DD + i] : 0.f;
    }

    float total = 0.f;

#pragma unroll
    for (int pass = 0; pass < 2; pass++) {
        float a[DD];
#pragma unroll
        for (int i = 0; i < DD; i++) a[i] = (pass == 0) ? qc[i] : pc[i];

        // Cholesky (lower), lane = row, fully unrolled, shuffle broadcasts
#pragma unroll
        for (int k = 0; k < DD; k++) {
            float dkk  = __shfl_sync(FULL, a[k], k);
            float linv = rsqrtf(dkk);
            float lk   = a[k] * linv;   // L[lane][k] for lane>=k
            a[k] = lk;
#pragma unroll
            for (int j = k + 1; j < DD; j++) {
                float ljk = __shfl_sync(FULL, lk, j);
                a[j] -= lk * ljk;
            }
        }

        float dinv[DD];
#pragma unroll
        for (int i = 0; i < DD; i++) dinv[i] = 1.f / __shfl_sync(FULL, a[i], i);

        // lane j computes column j of (L L^T)^{-1}
        float y[DD], x[DD];
#pragma unroll
        for (int i = 0; i < DD; i++) {
            float acc = (lane == i) ? 1.f : 0.f;
#pragma unroll
            for (int k = 0; k < i; k++) {
                float Lik = __shfl_sync(FULL, a[k], i);   // L[i][k]
                acc -= Lik * y[k];
            }
            y[i] = acc * dinv[i];
        }
#pragma unroll
        for (int i = DD - 1; i >= 0; i--) {
            float acc = y[i];
#pragma unroll
            for (int k = i + 1; k < DD; k++) {
                float Lki = __shfl_sync(FULL, a[i], k);   // L[k][i]
                acc -= Lki * x[k];
            }
            x[i] = acc * dinv[i];
        }

        float tr_c = 0.f, qd_c = 0.f;
#pragma unroll
        for (int i = 0; i < DD; i++) {
            float oc = (pass == 0) ? pc[i] : qc[i];
            tr_c += x[i] * oc;
            qd_c += x[i] * df[i];
        }
        float c = act ? (tr_c + dl * qd_c) : 0.f;
        total += c;
    }

#pragma unroll
    for (int o = 16; o > 0; o >>= 1) total += __shfl_down_sync(FULL, total, o);

    if (lane == 0) {
        float kl   = 0.25f * (total - 2.f * DD);
        float feat = logf(kl + 1e-5f);
        feat = (feat + 1.f) * mask[gw] - 1.f;
        g_feats[gw] = feat;
    }
}

// ==================== Kernel 3: BatchNorm over S=4 ====================
__global__ void bn_kernel(const float* __restrict__ gamma, const float* __restrict__ beta)
{
    int f = blockIdx.x * blockDim.x + threadIdx.x;
    if (f >= FF) return;
    float v0 = g_feats[f];
    float v1 = g_feats[FF + f];
    float v2 = g_feats[2 * FF + f];
    float v3 = g_feats[3 * FF + f];
    float mu = 0.25f * (v0 + v1 + v2 + v3);
    float d0 = v0 - mu, d1 = v1 - mu, d2 = v2 - mu, d3 = v3 - mu;
    float var = 0.25f * (d0 * d0 + d1 * d1 + d2 * d2 + d3 * d3);
    float sc  = rsqrtf(var + 1e-5f) * gamma[f];
    float bb  = beta[f];
    g_h0[f]          = d0 * sc + bb;
    g_h0[FF + f]     = d1 * sc + bb;
    g_h0[2 * FF + f] = d2 * sc + bb;
    g_h0[3 * FF + f] = d3 * sc + bb;
}

// ==================== Kernel 4: split-K GEMM partial ====================
// grid.x = KS (125). thread handles 4 adjacent output columns (float4 W loads).
// chunk = ceil(din/KS): 8 for din=1000, 10 for din=1128 (tail CTAs write zeros).
__global__ __launch_bounds__(256) void gemm_part(
    const float* __restrict__ hin, const float* __restrict__ W, int din, int dout)
{
    int tid = threadIdx.x;
    int nc4 = (dout + 3) >> 2;
    if (tid >= nc4) return;
    int c0 = tid * 4;
    int chunk = (din + KS - 1) / KS;
    int k0 = blockIdx.x * chunk;
    int k1 = min(din, k0 + chunk);

    float4 a0 = {0,0,0,0}, a1 = {0,0,0,0}, a2 = {0,0,0,0}, a3 = {0,0,0,0};
#pragma unroll 2
    for (int k = k0; k < k1; k++) {
        float4 w = __ldg(reinterpret_cast<const float4*>(W + (size_t)k * dout + c0));
        float h0 = __ldg(hin + k);
        float h1 = __ldg(hin + din + k);
        float h2 = __ldg(hin + 2 * din + k);
        float h3 = __ldg(hin + 3 * din + k);
        a0.x += h0 * w.x; a0.y += h0 * w.y; a0.z += h0 * w.z; a0.w += h0 * w.w;
        a1.x += h1 * w.x; a1.y += h1 * w.y; a1.z += h1 * w.z; a1.w += h1 * w.w;
        a2.x += h2 * w.x; a2.y += h2 * w.y; a2.z += h2 * w.z; a2.w += h2 * w.w;
        a3.x += h3 * w.x; a3.y += h3 * w.y; a3.z += h3 * w.z; a3.w += h3 * w.w;
    }
    float* P = g_partial + (size_t)blockIdx.x * 4 * dout;
    *reinterpret_cast<float4*>(P + 0 * dout + c0) = a0;
    *reinterpret_cast<float4*>(P + 1 * dout + c0) = a1;
    *reinterpret_cast<float4*>(P + 2 * dout + c0) = a2;
    *reinterpret_cast<float4*>(P + 3 * dout + c0) = a3;
}

// ==================== Kernel 5: split-K reduce + bias + relu (KS compile-time) ====================
__global__ void reduce_kernel(const float* __restrict__ bias, float* __restrict__ hout,
                              int relu)
{
    int idx = blockIdx.x * blockDim.x + threadIdx.x;
    if (idx >= 4 * HID) return;
    int c = idx % HID;
    float s = 0.f;
#pragma unroll
    for (int b = 0; b < KS; b++) s += g_partial[b * 4 * HID + idx];
    s += __ldg(bias + c);
    if (relu) s = fmaxf(s, 0.f);
    hout[idx] = s;
}

// ==================== Kernel 6: final layer (1000 -> 1) ====================
__global__ void final_kernel(const float* __restrict__ h, const float* __restrict__ W7,
                             const float* __restrict__ b7, float* __restrict__ out)
{
    const unsigned FULL = 0xffffffffu;
    int tid = threadIdx.x; // 128 threads
    float acc[4] = {0.f, 0.f, 0.f, 0.f};
    for (int k = tid; k < HID; k += 128) {
        float w = W7[k];
#pragma unroll
        for (int r = 0; r < 4; r++) acc[r] += h[r * HID + k] * w;
    }
#pragma unroll
    for (int r = 0; r < 4; r++) {
#pragma unroll
        for (int o = 16; o > 0; o >>= 1) acc[r] += __shfl_down_sync(FULL, acc[r], o);
    }
    __shared__ float red[4][4];
    int w = tid >> 5, lane = tid & 31;
    if (lane == 0) {
#pragma unroll
        for (int r = 0; r < 4; r++) red[w][r] = acc[r];
    }
    __syncthreads();
    if (tid < 4) {
        float s = red[0][tid] + red[1][tid] + red[2][tid] + red[3][tid] + b7[0];
        out[tid] = s;
    }
}

// ==================== launch ====================
extern "C" void kernel_launch(void* const* d_in, const int* in_sizes, int n_in,
                              void* d_out, int out_size)
{
    const float* p_vects = (const float*)d_in[0];
    const float* q_vects = (const float*)d_in[1];
    const float* p_len   = (const float*)d_in[2];
    const float* q_len   = (const float*)d_in[3];
    const float* mask    = (const float*)d_in[4];
    const float* gamma   = (const float*)d_in[5];
    const float* beta    = (const float*)d_in[6];
    const float* W1 = (const float*)d_in[7];  const float* b1 = (const float*)d_in[8];
    const float* W2 = (const float*)d_in[9];  const float* b2 = (const float*)d_in[10];
    const float* W3 = (const float*)d_in[11]; const float* b3 = (const float*)d_in[12];
    const float* W4 = (const float*)d_in[13]; const float* b4 = (const float*)d_in[14];
    const float* W5 = (const float*)d_in[15]; const float* b5 = (const float*)d_in[16];
    const float* W6 = (const float*)d_in[17]; const float* b6 = (const float*)d_in[18];
    const float* W7 = (const float*)d_in[19]; const float* b7 = (const float*)d_in[20];
    float* out = (float*)d_out;

    float* hA; cudaGetSymbolAddress((void**)&hA, g_hA);
    float* hB; cudaGetSymbolAddress((void**)&hB, g_hB);
    float* h0; cudaGetSymbolAddress((void**)&h0, g_h0);

    // 1. moments: one warp per tensor, 4 warps/CTA
    moments_kernel<<<NT / 4, 128>>>(p_vects, q_vects, p_len, q_len);

    // 2. symmetric KL: one warp per (s,f). 4512 warps = 564 blocks x 8 warps (exact)
    kl_kernel<<<SF / 8, 256>>>(mask);

    // 3. batch norm -> h0 [4,1128]
    bn_kernel<<<(FF + 255) / 256, 256>>>(gamma, beta);

    // 4. MLP (split-K = 125 CTAs per gemm)
    gemm_part<<<KS, 256>>>(h0, W1, FF, HID);
    reduce_kernel<<<(4 * HID + 255) / 256, 256>>>(b1, hA, 1);
    gemm_part<<<KS, 256>>>(hA, W2, HID, HID);
    reduce_kernel<<<(4 * HID + 255) / 256, 256>>>(b2, hB, 1);
    gemm_part<<<KS, 256>>>(hB, W3, HID, HID);
    reduce_kernel<<<(4 * HID + 255) / 256, 256>>>(b3, hA, 1);
    gemm_part<<<KS, 256>>>(hA, W4, HID, HID);
    reduce_kernel<<<(4 * HID + 255) / 256, 256>>>(b4, hB, 1);
    gemm_part<<<KS, 256>>>(hB, W5, HID, HID);
    reduce_kernel<<<(4 * HID + 255) / 256, 256>>>(b5, hA, 1);
    gemm_part<<<KS, 256>>>(hA, W6, HID, HID);
    reduce_kernel<<<(4 * HID + 255) / 256, 256>>>(b6, hB, 1);
    // layer 7: 1000 -> 1
    final_kernel<<<1, 128>>>(hB, W7, b7, out);
}